// round 5
// baseline (speedup 1.0000x reference)
#include <cuda_runtime.h>
#include <cuda_fp16.h>
#include <mma.h>
#include <cstdint>

using namespace nvcuda;

// ----------------------------------------------------------------------------
// out[M,N] = (A[M,K]_f32 @ W[N,K]_int8^T) * scale[N] + bias[N]
// M=8192, K=4096, N=11008.
// KEY FINDING (R4): harness materializes the int8 weight as INT32 (4B/elem).
// Reading it as char4 produced sign-extension garbage => rel_err 1.1182
// (= sqrt(1.25): uncorrelated output at half reference norm). Fix: int32 reads.
// compute_103 virtual arch (no 'a') => no tcgen05. wmma/HMMA path.
// ----------------------------------------------------------------------------

static constexpr int MDIM = 8192;
static constexpr int KDIM = 4096;
static constexpr int NDIM = 11008;

static constexpr int BM = 128;
static constexpr int BN = 256;
static constexpr int BK = 64;                   // halfs per K-chunk
static constexpr int STAGES = 3;
static constexpr int KITERS = KDIM / BK;        // 64

static constexpr int ROW_BYTES = 144;           // 64 halfs + 16B pad (ldm = 72)
static constexpr int LDM = 72;                  // halfs
static constexpr int A_STAGE_BYTES = BM * ROW_BYTES;              // 18432
static constexpr int B_STAGE_BYTES = BN * ROW_BYTES;              // 36864
static constexpr int STAGE_BYTES = A_STAGE_BYTES + B_STAGE_BYTES; // 55296
static constexpr int EPI_LDM = 68;              // floats
static constexpr int SMEM_BYTES = STAGES * STAGE_BYTES;           // 165888

static constexpr int MTILES = MDIM / BM;        // 64
static constexpr int NTILES = NDIM / BN;        // 43
static constexpr int THREADS = 256;

// fp16 scratch (device globals: no runtime allocation)
__device__ __half g_A[(size_t)MDIM * KDIM];     // 64 MiB
__device__ __half g_B[(size_t)NDIM * KDIM];     // 86 MiB

// ----------------------------------------------------------------------------
// helpers
// ----------------------------------------------------------------------------
__device__ __forceinline__ uint32_t smem_to_u32(const void* p) {
    uint32_t a;
    asm("{ .reg .u64 t; cvta.to.shared.u64 t, %1; cvt.u32.u64 %0, t; }"
        : "=r"(a) : "l"(p));
    return a;
}

#define CP_ASYNC_16(dst_u32, src_ptr) \
    asm volatile("cp.async.cg.shared.global [%0], [%1], 16;" \
                 :: "r"(dst_u32), "l"(src_ptr) : "memory")

#define CP_ASYNC_COMMIT() \
    asm volatile("cp.async.commit_group;" ::: "memory")

#define CP_ASYNC_WAIT_GROUP(n) \
    asm volatile("cp.async.wait_group %0;" :: "n"(n) : "memory")

// ----------------------------------------------------------------------------
// converts: fp32 -> fp16 (rounding ~3e-4 rel), int32 weight -> fp16 (exact)
// ----------------------------------------------------------------------------
__global__ void k_cvt_input(const float4* __restrict__ in) {
    int i = blockIdx.x * blockDim.x + threadIdx.x;   // exact grid sizing
    float4 v = in[i];
    __half2 h0 = __floats2half2_rn(v.x, v.y);
    __half2 h1 = __floats2half2_rn(v.z, v.w);
    uint2 u;
    u.x = *reinterpret_cast<uint32_t*>(&h0);
    u.y = *reinterpret_cast<uint32_t*>(&h1);
    reinterpret_cast<uint2*>(g_A)[i] = u;
}

__global__ void k_cvt_weight(const int4* __restrict__ in) {
    int i = blockIdx.x * blockDim.x + threadIdx.x;   // exact grid sizing
    int4 w = in[i];                                  // 4 x int32 (values in [-128,127])
    __half2 h0 = __floats2half2_rn((float)w.x, (float)w.y);
    __half2 h1 = __floats2half2_rn((float)w.z, (float)w.w);
    uint2 u;
    u.x = *reinterpret_cast<uint32_t*>(&h0);
    u.y = *reinterpret_cast<uint32_t*>(&h1);
    reinterpret_cast<uint2*>(g_B)[i] = u;
}

// ----------------------------------------------------------------------------
// GEMM: CTA 128x256, warp 64x64 (8 warps), 3-stage cp.async, wmma 16x16x16
// ----------------------------------------------------------------------------
__global__ void __launch_bounds__(THREADS, 1)
k_gemm(const float* __restrict__ scale, const float* __restrict__ bias,
       float* __restrict__ out)
{
    extern __shared__ char smem[];
    const uint32_t sb = smem_to_u32(smem);

    const int tid  = threadIdx.x;
    const int wid  = tid >> 5;
    const int lane = tid & 31;

    const int ntile = blockIdx.x % NTILES;
    const int mtile = blockIdx.x / NTILES;
    const int m0 = mtile * BM;
    const int n0 = ntile * BN;

    const int wm = (wid & 1) * 64;     // warp M offset within CTA tile
    const int wn = (wid >> 1) * 64;    // warp N offset within CTA tile

    // -------- producer: one K-chunk into stage s --------
    auto load_stage = [&](int s, int kt) {
        const __half* Ag = g_A + (size_t)m0 * KDIM + (size_t)kt * BK;
        const __half* Bg = g_B + (size_t)n0 * KDIM + (size_t)kt * BK;
        const uint32_t abase = sb + s * STAGE_BYTES;
        const uint32_t bbase = abase + A_STAGE_BYTES;
        #pragma unroll
        for (int j = 0; j < 4; j++) {              // A: 128 rows x 8 x 16B
            const int idx = tid + j * THREADS;
            const int row = idx >> 3;
            const int c   = idx & 7;
            CP_ASYNC_16(abase + row * ROW_BYTES + c * 16,
                        (const char*)(Ag + (size_t)row * KDIM) + c * 16);
        }
        #pragma unroll
        for (int j = 0; j < 8; j++) {              // B: 256 rows x 8 x 16B
            const int idx = tid + j * THREADS;
            const int row = idx >> 3;
            const int c   = idx & 7;
            CP_ASYNC_16(bbase + row * ROW_BYTES + c * 16,
                        (const char*)(Bg + (size_t)row * KDIM) + c * 16);
        }
    };

    // -------- prologue --------
    #pragma unroll
    for (int s = 0; s < STAGES - 1; s++) {
        load_stage(s, s);
        CP_ASYNC_COMMIT();
    }

    wmma::fragment<wmma::accumulator, 16, 16, 16, float> acc[4][4];
    #pragma unroll
    for (int mi = 0; mi < 4; mi++)
        #pragma unroll
        for (int ni = 0; ni < 4; ni++)
            wmma::fill_fragment(acc[mi][ni], 0.0f);

    // -------- mainloop --------
    for (int k = 0; k < KITERS; k++) {
        CP_ASYNC_WAIT_GROUP(STAGES - 2);
        __syncthreads();

        if (k + STAGES - 1 < KITERS)
            load_stage((k + STAGES - 1) % STAGES, k + STAGES - 1);
        CP_ASYNC_COMMIT();

        const __half* atile = reinterpret_cast<const __half*>(
            smem + (size_t)(k % STAGES) * STAGE_BYTES);
        const __half* btile = reinterpret_cast<const __half*>(
            smem + (size_t)(k % STAGES) * STAGE_BYTES + A_STAGE_BYTES);

        #pragma unroll
        for (int kk = 0; kk < 4; kk++) {           // 4 x k16 per 64-chunk
            const int kb = kk * 16;
            wmma::fragment<wmma::matrix_a, 16, 16, 16, __half, wmma::row_major> af[4];
            wmma::fragment<wmma::matrix_b, 16, 16, 16, __half, wmma::col_major> bf[4];
            #pragma unroll
            for (int mi = 0; mi < 4; mi++)
                wmma::load_matrix_sync(af[mi], atile + (size_t)(wm + mi * 16) * LDM + kb, LDM);
            #pragma unroll
            for (int ni = 0; ni < 4; ni++)
                wmma::load_matrix_sync(bf[ni], btile + (size_t)(wn + ni * 16) * LDM + kb, LDM);
            #pragma unroll
            for (int mi = 0; mi < 4; mi++)
                #pragma unroll
                for (int ni = 0; ni < 4; ni++)
                    wmma::mma_sync(acc[mi][ni], af[mi], bf[ni], acc[mi][ni]);
        }
    }

    // -------- epilogue: per-warp smem round trip, fused scale+bias --------
    __syncthreads();   // all warps done reading pipeline stages

    float* wbuf = reinterpret_cast<float*>(smem) + (size_t)wid * 64 * EPI_LDM;
    #pragma unroll
    for (int mi = 0; mi < 4; mi++)
        #pragma unroll
        for (int ni = 0; ni < 4; ni++)
            wmma::store_matrix_sync(wbuf + (size_t)(mi * 16) * EPI_LDM + ni * 16,
                                    acc[mi][ni], EPI_LDM, wmma::mem_row_major);
    __syncwarp();

    const int col = n0 + wn + lane * 2;
    const float2 sc2 = *reinterpret_cast<const float2*>(scale + col);
    const float2 bi2 = *reinterpret_cast<const float2*>(bias + col);

    #pragma unroll 4
    for (int r = 0; r < 64; r++) {
        const float2 v = *reinterpret_cast<const float2*>(wbuf + (size_t)r * EPI_LDM + lane * 2);
        float2 o;
        o.x = fmaf(v.x, sc2.x, bi2.x);
        o.y = fmaf(v.y, sc2.y, bi2.y);
        *reinterpret_cast<float2*>(out + (size_t)(m0 + wm + r) * NDIM + col) = o;
    }
}

// ----------------------------------------------------------------------------
// launch
// ----------------------------------------------------------------------------
extern "C" void kernel_launch(void* const* d_in, const int* in_sizes, int n_in,
                              void* d_out, int out_size)
{
    const float* input  = (const float*)d_in[0];   // [4,2048,4096] f32
    const int4*  weight = (const int4*)d_in[1];    // [11008,4096] int8 stored as int32
    const float* scale  = (const float*)d_in[2];   // [11008] f32
    const float* bias   = (const float*)d_in[3];   // [1,11008] f32
    float* out = (float*)d_out;

    (void)in_sizes; (void)n_in; (void)out_size;

    k_cvt_input<<<(MDIM * KDIM / 4) / 256, 256>>>((const float4*)input);
    k_cvt_weight<<<(NDIM * KDIM / 4) / 256, 256>>>(weight);

    cudaFuncSetAttribute(k_gemm, cudaFuncAttributeMaxDynamicSharedMemorySize,
                         SMEM_BYTES);
    k_gemm<<<MTILES * NTILES, THREADS, SMEM_BYTES>>>(scale, bias, out);
}

// round 6
// speedup vs baseline: 1.0572x; 1.0572x over previous
#include <cuda_runtime.h>
#include <cuda_fp16.h>
#include <mma.h>
#include <cstdint>

using namespace nvcuda;

// ----------------------------------------------------------------------------
// out[M,N] = (A[M,K]_f32 @ W[N,K]_int8^T) * scale[N] + bias[N]
// M=8192, K=4096, N=11008.
// Weight arrives as INT32 (harness materializes int8 as int32) -> int4 reads.
// compute_103 virtual arch (no 'a') => no tcgen05. wmma/HMMA path.
// R6: fragment double-buffering + 4-stage pipeline + MMA-first ordering.
// ----------------------------------------------------------------------------

static constexpr int MDIM = 8192;
static constexpr int KDIM = 4096;
static constexpr int NDIM = 11008;

static constexpr int BM = 128;
static constexpr int BN = 256;
static constexpr int BK = 64;                   // halfs per K-chunk
static constexpr int STAGES = 4;
static constexpr int KITERS = KDIM / BK;        // 64

static constexpr int ROW_BYTES = 144;           // 64 halfs + 16B pad (ldm = 72)
static constexpr int LDM = 72;                  // halfs
static constexpr int A_STAGE_BYTES = BM * ROW_BYTES;              // 18432
static constexpr int B_STAGE_BYTES = BN * ROW_BYTES;              // 36864
static constexpr int STAGE_BYTES = A_STAGE_BYTES + B_STAGE_BYTES; // 55296
static constexpr int EPI_LDM = 68;              // floats
static constexpr int SMEM_BYTES = STAGES * STAGE_BYTES;           // 221184

static constexpr int MTILES = MDIM / BM;        // 64
static constexpr int NTILES = NDIM / BN;        // 43
static constexpr int THREADS = 256;

// fp16 scratch (device globals: no runtime allocation)
__device__ __half g_A[(size_t)MDIM * KDIM];     // 64 MiB
__device__ __half g_B[(size_t)NDIM * KDIM];     // 86 MiB

// ----------------------------------------------------------------------------
// helpers
// ----------------------------------------------------------------------------
__device__ __forceinline__ uint32_t smem_to_u32(const void* p) {
    uint32_t a;
    asm("{ .reg .u64 t; cvta.to.shared.u64 t, %1; cvt.u32.u64 %0, t; }"
        : "=r"(a) : "l"(p));
    return a;
}

#define CP_ASYNC_16(dst_u32, src_ptr) \
    asm volatile("cp.async.cg.shared.global [%0], [%1], 16;" \
                 :: "r"(dst_u32), "l"(src_ptr) : "memory")

#define CP_ASYNC_COMMIT() \
    asm volatile("cp.async.commit_group;" ::: "memory")

#define CP_ASYNC_WAIT_GROUP(n) \
    asm volatile("cp.async.wait_group %0;" :: "n"(n) : "memory")

// ----------------------------------------------------------------------------
// converts: fp32 -> fp16 (rounding ~3e-4 rel), int32 weight -> fp16 (exact)
// ----------------------------------------------------------------------------
__global__ void k_cvt_input(const float4* __restrict__ in) {
    int i = blockIdx.x * blockDim.x + threadIdx.x;   // exact grid sizing
    float4 v = in[i];
    __half2 h0 = __floats2half2_rn(v.x, v.y);
    __half2 h1 = __floats2half2_rn(v.z, v.w);
    uint2 u;
    u.x = *reinterpret_cast<uint32_t*>(&h0);
    u.y = *reinterpret_cast<uint32_t*>(&h1);
    reinterpret_cast<uint2*>(g_A)[i] = u;
}

__global__ void k_cvt_weight(const int4* __restrict__ in) {
    int i = blockIdx.x * blockDim.x + threadIdx.x;   // exact grid sizing
    int4 w = in[i];                                  // 4 x int32, values in [-128,127]
    __half2 h0 = __floats2half2_rn((float)w.x, (float)w.y);
    __half2 h1 = __floats2half2_rn((float)w.z, (float)w.w);
    uint2 u;
    u.x = *reinterpret_cast<uint32_t*>(&h0);
    u.y = *reinterpret_cast<uint32_t*>(&h1);
    reinterpret_cast<uint2*>(g_B)[i] = u;
}

// ----------------------------------------------------------------------------
// GEMM: CTA 128x256, warp 64x64 (8 warps), 4-stage cp.async,
// wmma 16x16x16 with kk-level fragment double-buffering.
// ----------------------------------------------------------------------------
__global__ void __launch_bounds__(THREADS, 1)
k_gemm(const float* __restrict__ scale, const float* __restrict__ bias,
       float* __restrict__ out)
{
    extern __shared__ char smem[];
    const uint32_t sb = smem_to_u32(smem);

    const int tid  = threadIdx.x;
    const int wid  = tid >> 5;
    const int lane = tid & 31;

    const int ntile = blockIdx.x % NTILES;
    const int mtile = blockIdx.x / NTILES;
    const int m0 = mtile * BM;
    const int n0 = ntile * BN;

    const int wm = (wid & 1) * 64;     // warp M offset within CTA tile
    const int wn = (wid >> 1) * 64;    // warp N offset within CTA tile

    // -------- producer: one K-chunk into stage s --------
    auto load_stage = [&](int s, int kt) {
        const __half* Ag = g_A + (size_t)m0 * KDIM + (size_t)kt * BK;
        const __half* Bg = g_B + (size_t)n0 * KDIM + (size_t)kt * BK;
        const uint32_t abase = sb + s * STAGE_BYTES;
        const uint32_t bbase = abase + A_STAGE_BYTES;
        #pragma unroll
        for (int j = 0; j < 4; j++) {              // A: 128 rows x 8 x 16B
            const int idx = tid + j * THREADS;
            const int row = idx >> 3;
            const int c   = idx & 7;
            CP_ASYNC_16(abase + row * ROW_BYTES + c * 16,
                        (const char*)(Ag + (size_t)row * KDIM) + c * 16);
        }
        #pragma unroll
        for (int j = 0; j < 8; j++) {              // B: 256 rows x 8 x 16B
            const int idx = tid + j * THREADS;
            const int row = idx >> 3;
            const int c   = idx & 7;
            CP_ASYNC_16(bbase + row * ROW_BYTES + c * 16,
                        (const char*)(Bg + (size_t)row * KDIM) + c * 16);
        }
    };

    // -------- prologue: fill STAGES-1 stages --------
    #pragma unroll
    for (int s = 0; s < STAGES - 1; s++) {
        load_stage(s, s);
        CP_ASYNC_COMMIT();
    }

    wmma::fragment<wmma::accumulator, 16, 16, 16, float> acc[4][4];
    #pragma unroll
    for (int mi = 0; mi < 4; mi++)
        #pragma unroll
        for (int ni = 0; ni < 4; ni++)
            wmma::fill_fragment(acc[mi][ni], 0.0f);

    wmma::fragment<wmma::matrix_a, 16, 16, 16, __half, wmma::row_major> af[2][4];
    wmma::fragment<wmma::matrix_b, 16, 16, 16, __half, wmma::col_major> bf[2][4];

    // -------- mainloop --------
    for (int k = 0; k < KITERS; k++) {
        CP_ASYNC_WAIT_GROUP(STAGES - 2);   // stage k resident
        __syncthreads();

        const __half* atile = reinterpret_cast<const __half*>(
            smem + (size_t)(k % STAGES) * STAGE_BYTES);
        const __half* btile = reinterpret_cast<const __half*>(
            smem + (size_t)(k % STAGES) * STAGE_BYTES + A_STAGE_BYTES);

        // fragments for kk=0 FIRST (get tensor pipe going asap)
        #pragma unroll
        for (int mi = 0; mi < 4; mi++)
            wmma::load_matrix_sync(af[0][mi], atile + (size_t)(wm + mi * 16) * LDM, LDM);
        #pragma unroll
        for (int ni = 0; ni < 4; ni++)
            wmma::load_matrix_sync(bf[0][ni], btile + (size_t)(wn + ni * 16) * LDM, LDM);

        // then issue the next stage's global loads
        if (k + STAGES - 1 < KITERS)
            load_stage((k + STAGES - 1) % STAGES, k + STAGES - 1);
        CP_ASYNC_COMMIT();

        // kk pipeline: prefetch kk+1 fragments while doing kk's MMAs
        #pragma unroll
        for (int kk = 0; kk < 4; kk++) {
            const int cur = kk & 1;
            const int nxt = cur ^ 1;
            if (kk < 3) {
                const int kb = (kk + 1) * 16;
                #pragma unroll
                for (int mi = 0; mi < 4; mi++)
                    wmma::load_matrix_sync(af[nxt][mi],
                        atile + (size_t)(wm + mi * 16) * LDM + kb, LDM);
                #pragma unroll
                for (int ni = 0; ni < 4; ni++)
                    wmma::load_matrix_sync(bf[nxt][ni],
                        btile + (size_t)(wn + ni * 16) * LDM + kb, LDM);
            }
            #pragma unroll
            for (int mi = 0; mi < 4; mi++)
                #pragma unroll
                for (int ni = 0; ni < 4; ni++)
                    wmma::mma_sync(acc[mi][ni], af[cur][mi], bf[cur][ni], acc[mi][ni]);
        }
    }

    // -------- epilogue: per-warp smem round trip, fused scale+bias --------
    __syncthreads();   // all warps done reading pipeline stages

    float* wbuf = reinterpret_cast<float*>(smem) + (size_t)wid * 64 * EPI_LDM;
    #pragma unroll
    for (int mi = 0; mi < 4; mi++)
        #pragma unroll
        for (int ni = 0; ni < 4; ni++)
            wmma::store_matrix_sync(wbuf + (size_t)(mi * 16) * EPI_LDM + ni * 16,
                                    acc[mi][ni], EPI_LDM, wmma::mem_row_major);
    __syncwarp();

    const int col = n0 + wn + lane * 2;
    const float2 sc2 = *reinterpret_cast<const float2*>(scale + col);
    const float2 bi2 = *reinterpret_cast<const float2*>(bias + col);

    #pragma unroll 4
    for (int r = 0; r < 64; r++) {
        const float2 v = *reinterpret_cast<const float2*>(wbuf + (size_t)r * EPI_LDM + lane * 2);
        float2 o;
        o.x = fmaf(v.x, sc2.x, bi2.x);
        o.y = fmaf(v.y, sc2.y, bi2.y);
        *reinterpret_cast<float2*>(out + (size_t)(m0 + wm + r) * NDIM + col) = o;
    }
}

// ----------------------------------------------------------------------------
// launch
// ----------------------------------------------------------------------------
extern "C" void kernel_launch(void* const* d_in, const int* in_sizes, int n_in,
                              void* d_out, int out_size)
{
    const float* input  = (const float*)d_in[0];   // [4,2048,4096] f32
    const int4*  weight = (const int4*)d_in[1];    // [11008,4096] int8-as-int32
    const float* scale  = (const float*)d_in[2];   // [11008] f32
    const float* bias   = (const float*)d_in[3];   // [1,11008] f32
    float* out = (float*)d_out;

    (void)in_sizes; (void)n_in; (void)out_size;

    k_cvt_input<<<(MDIM * KDIM / 4) / 256, 256>>>((const float4*)input);
    k_cvt_weight<<<(NDIM * KDIM / 4) / 256, 256>>>(weight);

    cudaFuncSetAttribute(k_gemm, cudaFuncAttributeMaxDynamicSharedMemorySize,
                         SMEM_BYTES);
    k_gemm<<<MTILES * NTILES, THREADS, SMEM_BYTES>>>(scale, bias, out);
}

// round 7
// speedup vs baseline: 1.0665x; 1.0088x over previous
#include <cuda_runtime.h>
#include <cuda_fp16.h>
#include <cstdint>

// ----------------------------------------------------------------------------
// out[M,N] = (A[M,K]_f32 @ W[N,K]_int8^T) * scale[N] + bias[N]
// M=8192, K=4096, N=11008.
// Weight arrives as INT32 (harness materializes int8 as int32) -> int4 reads.
// compute_103 virtual arch (no 'a') => no tcgen05. Hand-rolled mma.sync path
// (wmma fragments are 2x-duplicated -> reg spills + 2x LDSM; mma.sync avoids).
// ----------------------------------------------------------------------------

static constexpr int MDIM = 8192;
static constexpr int KDIM = 4096;
static constexpr int NDIM = 11008;

static constexpr int BM = 128;
static constexpr int BN = 256;
static constexpr int BK = 64;                   // halfs per K-chunk
static constexpr int STAGES = 4;
static constexpr int KITERS = KDIM / BK;        // 64

static constexpr int ROW_BYTES = 144;           // 64 halfs + 16B pad
static constexpr int A_STAGE_BYTES = BM * ROW_BYTES;              // 18432
static constexpr int B_STAGE_BYTES = BN * ROW_BYTES;              // 36864
static constexpr int STAGE_BYTES = A_STAGE_BYTES + B_STAGE_BYTES; // 55296
static constexpr int SMEM_BYTES = STAGES * STAGE_BYTES;           // 221184

static constexpr int MTILES = MDIM / BM;        // 64
static constexpr int NTILES = NDIM / BN;        // 43
static constexpr int THREADS = 256;

// fp16 scratch (device globals: no runtime allocation)
__device__ __half g_A[(size_t)MDIM * KDIM];     // 64 MiB
__device__ __half g_B[(size_t)NDIM * KDIM];     // 86 MiB

// ----------------------------------------------------------------------------
// helpers
// ----------------------------------------------------------------------------
__device__ __forceinline__ uint32_t smem_to_u32(const void* p) {
    uint32_t a;
    asm("{ .reg .u64 t; cvta.to.shared.u64 t, %1; cvt.u32.u64 %0, t; }"
        : "=r"(a) : "l"(p));
    return a;
}

#define CP_ASYNC_16(dst_u32, src_ptr) \
    asm volatile("cp.async.cg.shared.global [%0], [%1], 16;" \
                 :: "r"(dst_u32), "l"(src_ptr) : "memory")

#define CP_ASYNC_COMMIT() \
    asm volatile("cp.async.commit_group;" ::: "memory")

#define CP_ASYNC_WAIT_GROUP(n) \
    asm volatile("cp.async.wait_group %0;" :: "n"(n) : "memory")

__device__ __forceinline__ void ldsm_x4(uint32_t* r, uint32_t addr) {
    asm volatile("ldmatrix.sync.aligned.m8n8.x4.shared.b16 {%0,%1,%2,%3}, [%4];"
                 : "=r"(r[0]), "=r"(r[1]), "=r"(r[2]), "=r"(r[3])
                 : "r"(addr));
}

__device__ __forceinline__ void mma16816(float* d, const uint32_t* a, const uint32_t* b) {
    asm volatile(
        "mma.sync.aligned.m16n8k16.row.col.f32.f16.f16.f32 "
        "{%0,%1,%2,%3}, {%4,%5,%6,%7}, {%8,%9}, {%0,%1,%2,%3};"
        : "+f"(d[0]), "+f"(d[1]), "+f"(d[2]), "+f"(d[3])
        : "r"(a[0]), "r"(a[1]), "r"(a[2]), "r"(a[3]), "r"(b[0]), "r"(b[1]));
}

// ----------------------------------------------------------------------------
// converts: fp32 -> fp16 (rounding ~3e-4 rel), int32 weight -> fp16 (exact)
// ----------------------------------------------------------------------------
__global__ void k_cvt_input(const float4* __restrict__ in) {
    int i = blockIdx.x * blockDim.x + threadIdx.x;   // exact grid sizing
    float4 v = in[i];
    __half2 h0 = __floats2half2_rn(v.x, v.y);
    __half2 h1 = __floats2half2_rn(v.z, v.w);
    uint2 u;
    u.x = *reinterpret_cast<uint32_t*>(&h0);
    u.y = *reinterpret_cast<uint32_t*>(&h1);
    reinterpret_cast<uint2*>(g_A)[i] = u;
}

__global__ void k_cvt_weight(const int4* __restrict__ in) {
    int i = blockIdx.x * blockDim.x + threadIdx.x;   // exact grid sizing
    int4 w = in[i];                                  // 4 x int32 in [-128,127]
    __half2 h0 = __floats2half2_rn((float)w.x, (float)w.y);
    __half2 h1 = __floats2half2_rn((float)w.z, (float)w.w);
    uint2 u;
    u.x = *reinterpret_cast<uint32_t*>(&h0);
    u.y = *reinterpret_cast<uint32_t*>(&h1);
    reinterpret_cast<uint2*>(g_B)[i] = u;
}

// ----------------------------------------------------------------------------
// GEMM: CTA 128x256, warp 64x64 (8 warps, 2x4), 4-stage cp.async,
// hand mma.sync m16n8k16 with kk-level fragment double buffering.
// ----------------------------------------------------------------------------
__global__ void __launch_bounds__(THREADS, 1)
k_gemm(const float* __restrict__ scale, const float* __restrict__ bias,
       float* __restrict__ out)
{
    extern __shared__ char smem[];
    const uint32_t sb = smem_to_u32(smem);

    const int tid  = threadIdx.x;
    const int wid  = tid >> 5;
    const int lane = tid & 31;

    const int ntile = blockIdx.x % NTILES;
    const int mtile = blockIdx.x / NTILES;
    const int m0 = mtile * BM;
    const int n0 = ntile * BN;

    const int wm = (wid & 1) * 64;     // warp M offset
    const int wn = (wid >> 1) * 64;    // warp N offset

    // producer: one K-chunk into stage s
    auto load_stage = [&](int s, int kt) {
        const __half* Ag = g_A + (size_t)m0 * KDIM + (size_t)kt * BK;
        const __half* Bg = g_B + (size_t)n0 * KDIM + (size_t)kt * BK;
        const uint32_t abase = sb + s * STAGE_BYTES;
        const uint32_t bbase = abase + A_STAGE_BYTES;
        #pragma unroll
        for (int j = 0; j < 4; j++) {              // A: 128 rows x 8 x 16B
            const int idx = tid + j * THREADS;
            const int row = idx >> 3;
            const int c   = idx & 7;
            CP_ASYNC_16(abase + row * ROW_BYTES + c * 16,
                        (const char*)(Ag + (size_t)row * KDIM) + c * 16);
        }
        #pragma unroll
        for (int j = 0; j < 8; j++) {              // B: 256 rows x 8 x 16B
            const int idx = tid + j * THREADS;
            const int row = idx >> 3;
            const int c   = idx & 7;
            CP_ASYNC_16(bbase + row * ROW_BYTES + c * 16,
                        (const char*)(Bg + (size_t)row * KDIM) + c * 16);
        }
    };

    // prologue: fill STAGES-1 stages
    #pragma unroll
    for (int s = 0; s < STAGES - 1; s++) {
        load_stage(s, s);
        CP_ASYNC_COMMIT();
    }

    float acc[4][8][4];
    #pragma unroll
    for (int mi = 0; mi < 4; mi++)
        #pragma unroll
        for (int ni = 0; ni < 8; ni++)
            #pragma unroll
            for (int r = 0; r < 4; r++) acc[mi][ni][r] = 0.0f;

    // ldmatrix lane addressing (verified against PTX fragment specs):
    // A x4: groups -> (rows0-7,k0-7),(rows8-15,k0-7),(rows0-7,k8-15),(rows8-15,k8-15)
    const int a_row_in = lane & 15;
    const int a_koff   = (lane >> 4) * 8;
    // B x4 on [n][k] smem: groups -> (n0-7,k0-7),(n0-7,k8-15),(n8-15,k0-7),(n8-15,k8-15)
    const int b_n_in   = ((lane >> 4) << 3) + (lane & 7);
    const int b_koff   = ((lane >> 3) & 1) * 8;

    uint32_t af[2][4][4];
    uint32_t bf[2][4][4];

    auto load_frags = [&](int buf, uint32_t abase, uint32_t bbase, int kb) {
        #pragma unroll
        for (int mi = 0; mi < 4; mi++) {
            const int row = wm + mi * 16 + a_row_in;
            ldsm_x4(af[buf][mi], abase + row * ROW_BYTES + (kb + a_koff) * 2);
        }
        #pragma unroll
        for (int p = 0; p < 4; p++) {
            const int nrow = wn + p * 16 + b_n_in;
            ldsm_x4(bf[buf][p], bbase + nrow * ROW_BYTES + (kb + b_koff) * 2);
        }
    };

    // mainloop
    for (int k = 0; k < KITERS; k++) {
        CP_ASYNC_WAIT_GROUP(STAGES - 2);   // chunk k resident
        __syncthreads();

        const uint32_t abase = sb + (k % STAGES) * STAGE_BYTES;
        const uint32_t bbase = abase + A_STAGE_BYTES;

        // kk=0 fragments first (tensor pipe starts asap)
        load_frags(0, abase, bbase, 0);

        // then next stage's global loads
        if (k + STAGES - 1 < KITERS)
            load_stage((k + STAGES - 1) % STAGES, k + STAGES - 1);
        CP_ASYNC_COMMIT();

        #pragma unroll
        for (int kk = 0; kk < 4; kk++) {
            const int cur = kk & 1;
            if (kk < 3)
                load_frags(cur ^ 1, abase, bbase, (kk + 1) * 16);
            #pragma unroll
            for (int mi = 0; mi < 4; mi++)
                #pragma unroll
                for (int ni = 0; ni < 8; ni++)
                    mma16816(acc[mi][ni], af[cur][mi], &bf[cur][ni >> 1][(ni & 1) * 2]);
        }
    }

    // epilogue: fused scale+bias, direct float2 stores
    float2 sc2[8], bi2[8];
    #pragma unroll
    for (int ni = 0; ni < 8; ni++) {
        const int col = n0 + wn + ni * 8 + (lane & 3) * 2;
        sc2[ni] = *reinterpret_cast<const float2*>(scale + col);
        bi2[ni] = *reinterpret_cast<const float2*>(bias + col);
    }

    #pragma unroll
    for (int mi = 0; mi < 4; mi++) {
        const int row0 = m0 + wm + mi * 16 + (lane >> 2);
        #pragma unroll
        for (int ni = 0; ni < 8; ni++) {
            const int col = n0 + wn + ni * 8 + (lane & 3) * 2;
            float2 v0, v1;
            v0.x = fmaf(acc[mi][ni][0], sc2[ni].x, bi2[ni].x);
            v0.y = fmaf(acc[mi][ni][1], sc2[ni].y, bi2[ni].y);
            v1.x = fmaf(acc[mi][ni][2], sc2[ni].x, bi2[ni].x);
            v1.y = fmaf(acc[mi][ni][3], sc2[ni].y, bi2[ni].y);
            *reinterpret_cast<float2*>(out + (size_t)row0 * NDIM + col) = v0;
            *reinterpret_cast<float2*>(out + (size_t)(row0 + 8) * NDIM + col) = v1;
        }
    }
}

// ----------------------------------------------------------------------------
// launch
// ----------------------------------------------------------------------------
extern "C" void kernel_launch(void* const* d_in, const int* in_sizes, int n_in,
                              void* d_out, int out_size)
{
    const float* input  = (const float*)d_in[0];   // [4,2048,4096] f32
    const int4*  weight = (const int4*)d_in[1];    // [11008,4096] int8-as-int32
    const float* scale  = (const float*)d_in[2];   // [11008] f32
    const float* bias   = (const float*)d_in[3];   // [1,11008] f32
    float* out = (float*)d_out;

    (void)in_sizes; (void)n_in; (void)out_size;

    k_cvt_input<<<(MDIM * KDIM / 4) / 256, 256>>>((const float4*)input);
    k_cvt_weight<<<(NDIM * KDIM / 4) / 256, 256>>>(weight);

    cudaFuncSetAttribute(k_gemm, cudaFuncAttributeMaxDynamicSharedMemorySize,
                         SMEM_BYTES);
    k_gemm<<<MTILES * NTILES, THREADS, SMEM_BYTES>>>(scale, bias, out);
}

// round 8
// speedup vs baseline: 1.2193x; 1.1433x over previous
#include <cuda_runtime.h>
#include <cuda_fp16.h>
#include <cstdint>

// ----------------------------------------------------------------------------
// out[M,N] = (A[M,K]_f32 @ W[N,K]_int8^T) * scale[N] + bias[N]
// M=8192, K=4096, N=11008.
// Weight arrives as INT32 (harness materializes int8 as int32) -> int4 reads.
// compute_103 (no 'a') => no tcgen05. Hand mma.sync m16n8k16 path.
// R8: occupancy-2 experiment — CTA 128x128, 3 stages, 110KB smem, <=128 regs.
// ----------------------------------------------------------------------------

static constexpr int MDIM = 8192;
static constexpr int KDIM = 4096;
static constexpr int NDIM = 11008;

static constexpr int BM = 128;
static constexpr int BN = 128;
static constexpr int BK = 64;                   // halfs per K-chunk
static constexpr int STAGES = 3;
static constexpr int KITERS = KDIM / BK;        // 64

static constexpr int ROW_BYTES = 144;           // 64 halfs + 16B pad
static constexpr int A_STAGE_BYTES = BM * ROW_BYTES;              // 18432
static constexpr int B_STAGE_BYTES = BN * ROW_BYTES;              // 18432
static constexpr int STAGE_BYTES = A_STAGE_BYTES + B_STAGE_BYTES; // 36864
static constexpr int SMEM_BYTES = STAGES * STAGE_BYTES;           // 110592

static constexpr int MTILES = MDIM / BM;        // 64
static constexpr int NTILES = NDIM / BN;        // 86
static constexpr int THREADS = 256;

// fp16 scratch (device globals: no runtime allocation)
__device__ __half g_A[(size_t)MDIM * KDIM];     // 64 MiB
__device__ __half g_B[(size_t)NDIM * KDIM];     // 86 MiB

// ----------------------------------------------------------------------------
// helpers
// ----------------------------------------------------------------------------
__device__ __forceinline__ uint32_t smem_to_u32(const void* p) {
    uint32_t a;
    asm("{ .reg .u64 t; cvta.to.shared.u64 t, %1; cvt.u32.u64 %0, t; }"
        : "=r"(a) : "l"(p));
    return a;
}

#define CP_ASYNC_16(dst_u32, src_ptr) \
    asm volatile("cp.async.cg.shared.global [%0], [%1], 16;" \
                 :: "r"(dst_u32), "l"(src_ptr) : "memory")

#define CP_ASYNC_COMMIT() \
    asm volatile("cp.async.commit_group;" ::: "memory")

#define CP_ASYNC_WAIT_GROUP(n) \
    asm volatile("cp.async.wait_group %0;" :: "n"(n) : "memory")

__device__ __forceinline__ void ldsm_x4(uint32_t* r, uint32_t addr) {
    asm volatile("ldmatrix.sync.aligned.m8n8.x4.shared.b16 {%0,%1,%2,%3}, [%4];"
                 : "=r"(r[0]), "=r"(r[1]), "=r"(r[2]), "=r"(r[3])
                 : "r"(addr));
}

__device__ __forceinline__ void mma16816(float* d, const uint32_t* a, const uint32_t* b) {
    asm volatile(
        "mma.sync.aligned.m16n8k16.row.col.f32.f16.f16.f32 "
        "{%0,%1,%2,%3}, {%4,%5,%6,%7}, {%8,%9}, {%0,%1,%2,%3};"
        : "+f"(d[0]), "+f"(d[1]), "+f"(d[2]), "+f"(d[3])
        : "r"(a[0]), "r"(a[1]), "r"(a[2]), "r"(a[3]), "r"(b[0]), "r"(b[1]));
}

// ----------------------------------------------------------------------------
// converts: fp32 -> fp16 (~3e-4 rel rounding), int32 weight -> fp16 (exact)
// ----------------------------------------------------------------------------
__global__ void k_cvt_input(const float4* __restrict__ in) {
    int i = blockIdx.x * blockDim.x + threadIdx.x;   // exact grid sizing
    float4 v = in[i];
    __half2 h0 = __floats2half2_rn(v.x, v.y);
    __half2 h1 = __floats2half2_rn(v.z, v.w);
    uint2 u;
    u.x = *reinterpret_cast<uint32_t*>(&h0);
    u.y = *reinterpret_cast<uint32_t*>(&h1);
    reinterpret_cast<uint2*>(g_A)[i] = u;
}

__global__ void k_cvt_weight(const int4* __restrict__ in) {
    int i = blockIdx.x * blockDim.x + threadIdx.x;   // exact grid sizing
    int4 w = in[i];                                  // 4 x int32 in [-128,127]
    __half2 h0 = __floats2half2_rn((float)w.x, (float)w.y);
    __half2 h1 = __floats2half2_rn((float)w.z, (float)w.w);
    uint2 u;
    u.x = *reinterpret_cast<uint32_t*>(&h0);
    u.y = *reinterpret_cast<uint32_t*>(&h1);
    reinterpret_cast<uint2*>(g_B)[i] = u;
}

// ----------------------------------------------------------------------------
// GEMM: CTA 128x128, warp 64x32 (8 warps, 2x4), 3-stage cp.async, occ=2
// ----------------------------------------------------------------------------
__global__ void __launch_bounds__(THREADS, 2)
k_gemm(const float* __restrict__ scale, const float* __restrict__ bias,
       float* __restrict__ out)
{
    extern __shared__ char smem[];
    const uint32_t sb = smem_to_u32(smem);

    const int tid  = threadIdx.x;
    const int wid  = tid >> 5;
    const int lane = tid & 31;

    const int ntile = blockIdx.x % NTILES;
    const int mtile = blockIdx.x / NTILES;
    const int m0 = mtile * BM;
    const int n0 = ntile * BN;

    const int wm = (wid & 1) * 64;     // warp M offset (2 warps in M)
    const int wn = (wid >> 1) * 32;    // warp N offset (4 warps in N)

    // producer: one K-chunk into stage s (8 cp.async per thread)
    auto load_stage = [&](int s, int kt) {
        const __half* Ag = g_A + (size_t)m0 * KDIM + (size_t)kt * BK;
        const __half* Bg = g_B + (size_t)n0 * KDIM + (size_t)kt * BK;
        const uint32_t abase = sb + s * STAGE_BYTES;
        const uint32_t bbase = abase + A_STAGE_BYTES;
        #pragma unroll
        for (int j = 0; j < 4; j++) {              // A: 128 rows x 8 x 16B
            const int idx = tid + j * THREADS;
            const int row = idx >> 3;
            const int c   = idx & 7;
            CP_ASYNC_16(abase + row * ROW_BYTES + c * 16,
                        (const char*)(Ag + (size_t)row * KDIM) + c * 16);
        }
        #pragma unroll
        for (int j = 0; j < 4; j++) {              // B: 128 rows x 8 x 16B
            const int idx = tid + j * THREADS;
            const int row = idx >> 3;
            const int c   = idx & 7;
            CP_ASYNC_16(bbase + row * ROW_BYTES + c * 16,
                        (const char*)(Bg + (size_t)row * KDIM) + c * 16);
        }
    };

    // prologue: fill STAGES-1 stages
    #pragma unroll
    for (int s = 0; s < STAGES - 1; s++) {
        load_stage(s, s);
        CP_ASYNC_COMMIT();
    }

    float acc[4][4][4];
    #pragma unroll
    for (int mi = 0; mi < 4; mi++)
        #pragma unroll
        for (int ni = 0; ni < 4; ni++)
            #pragma unroll
            for (int r = 0; r < 4; r++) acc[mi][ni][r] = 0.0f;

    // ldmatrix lane addressing
    const int a_row_in = lane & 15;
    const int a_koff   = (lane >> 4) * 8;
    const int b_n_in   = ((lane >> 4) << 3) + (lane & 7);
    const int b_koff   = ((lane >> 3) & 1) * 8;

    // mainloop
    for (int k = 0; k < KITERS; k++) {
        CP_ASYNC_WAIT_GROUP(STAGES - 2);   // chunk k resident (this thread)
        __syncthreads();                   // visible CTA-wide

        const uint32_t abase = sb + (k % STAGES) * STAGE_BYTES;
        const uint32_t bbase = abase + A_STAGE_BYTES;

        #pragma unroll
        for (int kk = 0; kk < 4; kk++) {
            const int kb = kk * 16;
            uint32_t af[4][4];
            uint32_t bf[2][4];
            #pragma unroll
            for (int mi = 0; mi < 4; mi++) {
                const int row = wm + mi * 16 + a_row_in;
                ldsm_x4(af[mi], abase + row * ROW_BYTES + (kb + a_koff) * 2);
            }
            #pragma unroll
            for (int p = 0; p < 2; p++) {
                const int nrow = wn + p * 16 + b_n_in;
                ldsm_x4(bf[p], bbase + nrow * ROW_BYTES + (kb + b_koff) * 2);
            }
            // overlap next-stage issue behind kk=0's MMAs
            if (kk == 0) {
                if (k + STAGES - 1 < KITERS)
                    load_stage((k + STAGES - 1) % STAGES, k + STAGES - 1);
                CP_ASYNC_COMMIT();
            }
            #pragma unroll
            for (int mi = 0; mi < 4; mi++)
                #pragma unroll
                for (int ni = 0; ni < 4; ni++)
                    mma16816(acc[mi][ni], af[mi], &bf[ni >> 1][(ni & 1) * 2]);
        }
    }

    // epilogue: fused scale+bias, direct float2 stores
    float2 sc2[4], bi2[4];
    #pragma unroll
    for (int ni = 0; ni < 4; ni++) {
        const int col = n0 + wn + ni * 8 + (lane & 3) * 2;
        sc2[ni] = *reinterpret_cast<const float2*>(scale + col);
        bi2[ni] = *reinterpret_cast<const float2*>(bias + col);
    }

    #pragma unroll
    for (int mi = 0; mi < 4; mi++) {
        const int row0 = m0 + wm + mi * 16 + (lane >> 2);
        #pragma unroll
        for (int ni = 0; ni < 4; ni++) {
            const int col = n0 + wn + ni * 8 + (lane & 3) * 2;
            float2 v0, v1;
            v0.x = fmaf(acc[mi][ni][0], sc2[ni].x, bi2[ni].x);
            v0.y = fmaf(acc[mi][ni][1], sc2[ni].y, bi2[ni].y);
            v1.x = fmaf(acc[mi][ni][2], sc2[ni].x, bi2[ni].x);
            v1.y = fmaf(acc[mi][ni][3], sc2[ni].y, bi2[ni].y);
            *reinterpret_cast<float2*>(out + (size_t)row0 * NDIM + col) = v0;
            *reinterpret_cast<float2*>(out + (size_t)(row0 + 8) * NDIM + col) = v1;
        }
    }
}

// ----------------------------------------------------------------------------
// launch
// ----------------------------------------------------------------------------
extern "C" void kernel_launch(void* const* d_in, const int* in_sizes, int n_in,
                              void* d_out, int out_size)
{
    const float* input  = (const float*)d_in[0];   // [4,2048,4096] f32
    const int4*  weight = (const int4*)d_in[1];    // [11008,4096] int8-as-int32
    const float* scale  = (const float*)d_in[2];   // [11008] f32
    const float* bias   = (const float*)d_in[3];   // [1,11008] f32
    float* out = (float*)d_out;

    (void)in_sizes; (void)n_in; (void)out_size;

    k_cvt_input<<<(MDIM * KDIM / 4) / 256, 256>>>((const float4*)input);
    k_cvt_weight<<<(NDIM * KDIM / 4) / 256, 256>>>(weight);

    cudaFuncSetAttribute(k_gemm, cudaFuncAttributeMaxDynamicSharedMemorySize,
                         SMEM_BYTES);
    k_gemm<<<MTILES * NTILES, THREADS, SMEM_BYTES>>>(scale, bias, out);
}